// round 11
// baseline (speedup 1.0000x reference)
#include <cuda_runtime.h>
#include <cuda_bf16.h>

// Soft-label distillation transform:
//   per row i: S = sum_j logits[i,j]; t = logits[i,label_i];
//   s = 0.95 / (1 + S - 2t)
//   out[i, j]     = s * logits[i,j]      (j != label)
//   out[i, label] = s*t + (1 - s*S)
//
// B=4096 rows, C=32000 cols, fp32 in/out, labels int32.
//
// R8 (161us, DRAM=81.5%): SMEM-staged + register prefetch. Insight: each
// thread read back from SMEM exactly the indices it wrote — the 128KB
// round-trip carried no cross-thread data except row[label].
//
// R9..R11: pure register pipeline, no SMEM data staging.
//  - r[8] float4 holds the row; sum phase reads registers directly.
//  - store loop fuses: consume r[k] -> issue r[k] = load(next row, k)
//    -> scale/patch/store. Reads of row n+1 interleave with writes of
//    row n: continuous mixed DRAM stream, no per-row read burst.
//  - t published via one smem float by the owning thread (unrolled
//    ownership test; owner tid = lvec & 1023, k = lvec >> 10, unique).
//  - 2 barriers/row; sS/sT parity-buffered. Audited: rewriting slot p
//    requires passing both barriers of iter n+1, which postdates every
//    thread's register-capture of iter n's S,t.
//  - R11: incremental pointer arithmetic (constant stride bump per row)
//    instead of per-row 64-bit b*NVEC recompute — fewer live temps,
//    lower spill risk against the 64-reg cap.
// HBM traffic stays at the 1.05 GB floor. __ldcs/__stcs: touched-once.

#define BATCH 4096
#define NUM_CLASSES 32000
#define NVEC (NUM_CLASSES / 4)   // 8000 float4 per row
#define NTHREADS 1024
#define ALPHA 0.95f

__global__ __launch_bounds__(NTHREADS, 1)
void distill_kernel(const float* __restrict__ logits,
                    const int* __restrict__ labels,
                    float* __restrict__ out)
{
    __shared__ float warpsum[32];
    __shared__ float sS[2];      // parity-buffered row scalars
    __shared__ float sT[2];

    const int  tid    = threadIdx.x;
    const bool lastok = (tid + 7 * NTHREADS) < NVEC;   // k=7 chunk valid?
    const long stride = (long)gridDim.x * NVEC;        // float4s per row-step

    float4 r[8];

    // Per-CTA base pointers (thread-offset folded in once).
    const float4* nin4 = reinterpret_cast<const float4*>(logits)
                         + (size_t)blockIdx.x * NVEC + tid;
    float4*       out4 = reinterpret_cast<float4*>(out)
                         + (size_t)blockIdx.x * NVEC + tid;

    // Prologue: load first row + its label.
    #pragma unroll
    for (int k = 0; k < 7; k++) r[k] = __ldcs(nin4 + k * NTHREADS);
    if (lastok)                r[7] = __ldcs(nin4 + 7 * NTHREADS);
    nin4 += stride;                                // now points at next row
    int label = __ldg(&labels[blockIdx.x]);

    int p = 0;                                     // row parity
    for (int b = blockIdx.x; b < BATCH; b += gridDim.x, p ^= 1) {
        const int nb    = b + gridDim.x;
        const int lvec  = label >> 2;
        const int llane = label & 3;

        // Sum phase: registers only. Owner thread publishes t.
        float lsum = 0.0f;
        #pragma unroll
        for (int k = 0; k < 8; k++) {
            if (k == 7 && !lastok) break;
            float4 v = r[k];
            lsum += (v.x + v.y) + (v.z + v.w);
            if (tid + k * NTHREADS == lvec) {      // unrolled: constant k
                sT[p] = (llane == 0) ? v.x : (llane == 1) ? v.y
                      : (llane == 2) ? v.z : v.w;
            }
        }

        // Block reduction of S.
        #pragma unroll
        for (int o = 16; o > 0; o >>= 1)
            lsum += __shfl_xor_sync(0xFFFFFFFFu, lsum, o);
        if ((tid & 31) == 0) warpsum[tid >> 5] = lsum;
        __syncthreads();                           // bar1: warpsum + sT visible
        if (tid < 32) {
            float v = warpsum[tid];
            #pragma unroll
            for (int o = 16; o > 0; o >>= 1)
                v += __shfl_xor_sync(0xFFFFFFFFu, v, o);
            if (tid == 0) sS[p] = v;
        }
        __syncthreads();                           // bar2: sS visible

        const float S    = sS[p];
        const float t    = sT[p];
        const float s    = ALPHA / (1.0f + S - 2.0f * t);
        const float corr = 1.0f - s * S;
        const bool  more = (nb < BATCH);

        if (more) label = __ldg(&labels[nb]);      // next label, early

        // Fused store + prefetch loop: writes row b, reads row nb.
        #pragma unroll
        for (int k = 0; k < 8; k++) {
            const int i = tid + k * NTHREADS;
            if (k == 7 && !lastok) break;
            float4 v = r[k];                       // consume current row
            if (more) r[k] = __ldcs(nin4 + k * NTHREADS);  // refill next row
            v.x *= s; v.y *= s; v.z *= s; v.w *= s;
            if (i == lvec) {                       // ISETP + @P FADD
                float* vf = reinterpret_cast<float*>(&v);
                vf[llane] += corr;
            }
            __stcs(out4 + k * NTHREADS, v);
        }
        nin4 += stride;
        out4 += stride;
        // sS/sT parity buffering closes the reuse race; no 3rd barrier.
    }
}

extern "C" void kernel_launch(void* const* d_in, const int* in_sizes, int n_in,
                              void* d_out, int out_size)
{
    const float* logits = (const float*)d_in[0];
    const int*   labels = (const int*)d_in[1];
    float*       out    = (float*)d_out;

    // Persistent grid: exactly #SMs (152 on GB300). Never more — at
    // 1 CTA/SM occupancy a surplus CTA would serialize behind a full loop.
    int dev = 0, nsm = 148;
    (void)cudaGetDevice(&dev);
    (void)cudaDeviceGetAttribute(&nsm, cudaDevAttrMultiProcessorCount, dev);
    int grid = nsm < BATCH ? nsm : BATCH;

    distill_kernel<<<grid, NTHREADS>>>(logits, labels, out);
}

// round 14
// speedup vs baseline: 1.0495x; 1.0495x over previous
#include <cuda_runtime.h>
#include <cuda_bf16.h>

// Soft-label distillation transform:
//   per row i: S = sum_j logits[i,j]; t = logits[i,label_i];
//   s = 0.95 / (1 + S - 2t)
//   out[i, j]     = s * logits[i,j]      (j != label)
//   out[i, label] = s*t + (1 - s*S)
//
// B=4096 rows, C=32000 cols, fp32 in/out, labels int32.
//
// History: R8 (SMEM-staged, batched prefetch burst) = 161us, DRAM 81.5%.
// R11 (fused consume/refill/store) = 185us, DRAM 69.4% — REGRESSION:
// late-chunk refills had no latency cover, and fine-grained read/write
// interleave paid DRAM turnaround. Burst-per-phase wins.
//
// R12..R14 = R8 structure + two audit fixes:
//  1. row4 is THREAD-PRIVATE (each thread stores/reloads its own
//     indices; cross-thread SMEM is only warpsum/sS/t). The refill LDG
//     for chunk k issues right after chunk k drains (STS;LDG in
//     staging) — the DRAM read stream restarts ~1000cyc earlier per
//     row. Refill cover: rest of staging + reduction + store phase
//     (>=3Kcyc even for k=7) — the R11 failure mode is absent.
//  2. Third barrier deleted (row4 private). 2 barriers/row; sS/sT
//     parity-buffered (slot p rewritten only after both barriers of
//     iter n+1, postdating all register captures of iter n's S,t).
//     t published by the unique owner (tid = lvec & 1023, k = lvec>>10).
//
// Read bursts (staging) and write bursts (store phase) stay separated.
// HBM traffic at the 1.05 GB floor. __ldcs/__stcs: touched-once data.

#define BATCH 4096
#define NUM_CLASSES 32000
#define NVEC (NUM_CLASSES / 4)   // 8000 float4 per row
#define NTHREADS 1024
#define ALPHA 0.95f

__global__ __launch_bounds__(NTHREADS, 1)
void distill_kernel(const float* __restrict__ logits,
                    const int* __restrict__ labels,
                    float* __restrict__ out)
{
    extern __shared__ float row[];                 // 128 KB, thread-private use
    __shared__ float warpsum[32];
    __shared__ float sS[2];                        // parity-buffered scalars
    __shared__ float sT[2];

    const int  tid    = threadIdx.x;
    const bool lastok = (tid + 7 * NTHREADS) < NVEC;   // k=7 chunk valid?
    const long stride = (long)gridDim.x * NVEC;        // float4s per row-step
    float4* row4 = reinterpret_cast<float4*>(row);

    float4 r[8];

    // Per-CTA pointers with thread offset folded in.
    const float4* nin4 = reinterpret_cast<const float4*>(logits)
                         + (size_t)blockIdx.x * NVEC + tid;
    float4*       out4 = reinterpret_cast<float4*>(out)
                         + (size_t)blockIdx.x * NVEC + tid;

    // Prologue: load first row + its label.
    #pragma unroll
    for (int k = 0; k < 7; k++) r[k] = __ldcs(nin4 + k * NTHREADS);
    if (lastok)                r[7] = __ldcs(nin4 + 7 * NTHREADS);
    nin4 += stride;                                // -> next row
    int label = __ldg(&labels[blockIdx.x]);

    int p = 0;                                     // row parity
    for (int b = blockIdx.x; b < BATCH; b += gridDim.x, p ^= 1) {
        const int  nb    = b + gridDim.x;
        const int  lvec  = label >> 2;
        const int  llane = label & 3;
        const bool more  = (nb < BATCH);

        // Staging: per chunk — drain r[k] to smem + sum, then IMMEDIATELY
        // refill r[k] from the next row (read stream never pauses).
        float lsum = 0.0f;
        #pragma unroll
        for (int k = 0; k < 8; k++) {
            if (k == 7 && !lastok) break;
            const int i = tid + k * NTHREADS;
            float4 v = r[k];
            if (more) r[k] = __ldcs(nin4 + k * NTHREADS);   // refill burst
            row4[i] = v;                                     // STS (private)
            lsum += (v.x + v.y) + (v.z + v.w);
            if (i == lvec) {                                 // unique owner
                sT[p] = (llane == 0) ? v.x : (llane == 1) ? v.y
                      : (llane == 2) ? v.z : v.w;
            }
        }

        // Block reduction of S.
        #pragma unroll
        for (int o = 16; o > 0; o >>= 1)
            lsum += __shfl_xor_sync(0xFFFFFFFFu, lsum, o);
        if ((tid & 31) == 0) warpsum[tid >> 5] = lsum;
        __syncthreads();                           // bar1: warpsum + sT
        if (tid < 32) {
            float v = warpsum[tid];
            #pragma unroll
            for (int o = 16; o > 0; o >>= 1)
                v += __shfl_xor_sync(0xFFFFFFFFu, v, o);
            if (tid == 0) sS[p] = v;
        }
        __syncthreads();                           // bar2: sS

        const float S    = sS[p];
        const float t    = sT[p];
        const float s    = ALPHA / (1.0f + S - 2.0f * t);
        const float corr = 1.0f - s * S;

        if (more) label = __ldg(&labels[nb]);      // next label, covered here

        // Store phase: read own smem slots, scale, patch, stream out.
        #pragma unroll
        for (int k = 0; k < 8; k++) {
            if (k == 7 && !lastok) break;
            const int i = tid + k * NTHREADS;
            float4 v = row4[i];                    // LDS (private, no conflicts)
            v.x *= s; v.y *= s; v.z *= s; v.w *= s;
            if (i == lvec) {                       // ISETP + @P FADD
                float* vf = reinterpret_cast<float*>(&v);
                vf[llane] += corr;
            }
            __stcs(out4 + k * NTHREADS, v);
        }
        nin4 += stride;
        out4 += stride;
        // No 3rd barrier: row4 slots are thread-private; sS/sT parity-
        // buffered; warpsum rewrite gated by bar2 of this iteration.
    }
}

extern "C" void kernel_launch(void* const* d_in, const int* in_sizes, int n_in,
                              void* d_out, int out_size)
{
    const float* logits = (const float*)d_in[0];
    const int*   labels = (const int*)d_in[1];
    float*       out    = (float*)d_out;

    const int smem_bytes = NUM_CLASSES * sizeof(float);   // 128000 B dynamic
    (void)cudaFuncSetAttribute(distill_kernel,
                               cudaFuncAttributeMaxDynamicSharedMemorySize,
                               smem_bytes);

    // Persistent grid: exactly #SMs (152 on GB300). Never more — at
    // 1 CTA/SM occupancy a surplus CTA would serialize behind a full loop.
    int dev = 0, nsm = 148;
    (void)cudaGetDevice(&dev);
    (void)cudaDeviceGetAttribute(&nsm, cudaDevAttrMultiProcessorCount, dev);
    int grid = nsm < BATCH ? nsm : BATCH;

    distill_kernel<<<grid, NTHREADS, smem_bytes>>>(logits, labels, out);
}